// round 15
// baseline (speedup 1.0000x reference)
#include <cuda_runtime.h>
#include <cuda_bf16.h>
#include <math.h>

// ---------------- problem constants ----------------
#define BB 8
#define TT 60
#define NN 400
#define FF 64
#define UU 64
#define KLEN 12
#define BT (BB*TT)        // 480
#define KMAX 64
#define TPAD 72           // az rows per node: row = t + dt, t in [0,60), dt in [0,12)
#define AZW 132           // az row stride in floats (132 % 32 == 4 -> conflict-free frags)
#define KSTEPS (KLEN*16)  // 192 k-steps of 8
#define NPC 4             // nodes per CTA in k4
#define DROWS (NPC*TPAD)  // dummy zero-row base (12 rows)
#define AZROWS (NPC*TPAD + 12)   // 300

// ---------------- device scratch (no runtime alloc allowed) ----------------
__device__ float g_W2t[NN*FF];        // W2t[j][f] = dgc_W2[f][j]
__device__ int   g_ridx[NN*KMAX];
__device__ float g_radj[NN*KMAX];
__device__ int   g_rlen[NN];
__device__ int   g_cidx[NN*KMAX];
__device__ float g_cval[NN*KMAX];
__device__ int   g_clen[NN];
__device__ float g_nodef[BT*NN*UU];   // attn @ x (pre-W3), ~49 MB
__device__ float g_lhs[BT*NN];
__device__ float g_rhs[BT*NN];
__device__ float g_sg [BB*TT*TT];
__device__ float g_ker[BB*TT*TT];
// W3-folded artifacts
__device__ float g_tkW3[KLEN*FF*UU];  // tkW3[dt][f][u] = sum_c W3[f][c]*tk[dt][c][u]
__device__ float g_w3v[UU];           // W3 @ taW3
__device__ float g_scal[2];           // [0]=sum(taW1), [1]=b2.taW3
__device__ float g_lbias[NN];         // S1 * (b2 @ taW2)
__device__ float g_lhsW[FF*NN];       // lhsW[f][n] = sum_c W3[f][c]*taW2[c][n]
__device__ float g_tbias[KLEN*UU];    // per-dt conv bias from b2
__device__ float g_bc[TT*UU];         // conv bias from b2 (edge-dependent)
// Pre-packed tf32 B-fragments: [(kstep*8 + nt)*32 + lane] = {B[k0+l%4][n], B[k0+4+l%4][n]}
__device__ float2 g_wfrag[KSTEPS*8*32];   // 393 KB

// ---------------- helpers ----------------
__device__ __forceinline__ unsigned long long packf2(float x, float y) {
    unsigned long long r;
    asm("mov.b64 %0, {%1, %2};" : "=l"(r) : "f"(x), "f"(y));
    return r;
}
__device__ __forceinline__ void unpackf2(unsigned long long v, float& x, float& y) {
    asm("mov.b64 {%0, %1}, %2;" : "=f"(x), "=f"(y) : "l"(v));
}
__device__ __forceinline__ void ffma2(unsigned long long& d, unsigned long long a, unsigned long long b) {
    asm("fma.rn.f32x2 %0, %1, %2, %0;" : "+l"(d) : "l"(a), "l"(b));
}
__device__ __forceinline__ unsigned tf32r(float x) {
    unsigned r; asm("cvt.rna.tf32.f32 %0, %1;" : "=r"(r) : "f"(x)); return r;
}
__device__ __forceinline__ void mma_tf32(float* c, unsigned a0, unsigned a1,
                                         unsigned a2, unsigned a3,
                                         unsigned b0, unsigned b1) {
    asm("mma.sync.aligned.m16n8k8.row.col.f32.tf32.tf32.f32 "
        "{%0,%1,%2,%3}, {%4,%5,%6,%7}, {%8,%9}, {%0,%1,%2,%3};"
        : "+f"(c[0]), "+f"(c[1]), "+f"(c[2]), "+f"(c[3])
        : "r"(a0), "r"(a1), "r"(a2), "r"(a3), "r"(b0), "r"(b1));
}
__device__ __forceinline__ float warp_sum(float v) {
    #pragma unroll
    for (int o = 16; o; o >>= 1) v += __shfl_xor_sync(0xffffffffu, v, o);
    return v;
}
__device__ __forceinline__ float warp_max(float v) {
    #pragma unroll
    for (int o = 16; o; o >>= 1) v = fmaxf(v, __shfl_xor_sync(0xffffffffu, v, o));
    return v;
}
// Reduce 8 per-lane partials across the warp in 9 SHFL.
__device__ __forceinline__ float multi_reduce8(const float* pp, int lane) {
    float q[4];
    bool b4 = (lane & 4) != 0;
    #pragma unroll
    for (int i = 0; i < 4; i++) {
        float send = b4 ? pp[i] : pp[i + 4];
        float recv = __shfl_xor_sync(0xffffffffu, send, 4);
        q[i] = (b4 ? pp[i + 4] : pp[i]) + recv;
    }
    float r[2];
    bool b2 = (lane & 2) != 0;
    #pragma unroll
    for (int i = 0; i < 2; i++) {
        float send = b2 ? q[i] : q[i + 2];
        float recv = __shfl_xor_sync(0xffffffffu, send, 2);
        r[i] = (b2 ? q[i + 2] : q[i]) + recv;
    }
    bool b1 = (lane & 1) != 0;
    float send = b1 ? r[0] : r[1];
    float recv = __shfl_xor_sync(0xffffffffu, send, 1);
    float v = (b1 ? r[1] : r[0]) + recv;
    v += __shfl_xor_sync(0xffffffffu, v, 8);
    v += __shfl_xor_sync(0xffffffffu, v, 16);
    return v;
}
__device__ __forceinline__ float softplusf(float z) {
    return fmaxf(z, 0.f) + log1pf(expf(-fabsf(z)));
}

// ---------------- K0w: fold W3 into tconv weights ----------------
__global__ void k0w_fold(const float* __restrict__ tk, const float* __restrict__ W3) {
    int dt = blockIdx.x >> 6, f = blockIdx.x & 63, u = threadIdx.x;
    float acc = 0.f;
    #pragma unroll 4
    for (int c = 0; c < 64; c++)
        acc += W3[f*64 + c] * tk[(dt*64 + c)*64 + u];
    g_tkW3[(dt*64 + f)*64 + u] = acc;
}

// ---------------- K0: CSR build + W2 transpose ----------------
__global__ void k0_build(const float* __restrict__ A, const float* __restrict__ W1,
                         const float* __restrict__ W2) {
    int m = blockIdx.x;
    int lane = threadIdx.x;
    int cnt = 0;
    for (int j0 = 0; j0 < NN; j0 += 32) {
        int j = j0 + lane;
        float a = (j < NN) ? A[m*NN + j] : 0.f;
        unsigned mask = __ballot_sync(0xffffffffu, a != 0.f);
        int pos = cnt + __popc(mask & ((1u << lane) - 1u));
        if (a != 0.f && pos < KMAX) {
            g_ridx[m*KMAX + pos] = j;
            g_radj[m*KMAX + pos] = -1e16f * (1.f - a);
        }
        cnt += __popc(mask);
    }
    if (lane == 0) g_rlen[m] = min(cnt, KMAX);
    cnt = 0;
    for (int n0 = 0; n0 < NN; n0 += 32) {
        int n = n0 + lane;
        float a = (n < NN) ? A[n*NN + m] : 0.f;
        unsigned mask = __ballot_sync(0xffffffffu, a != 0.f);
        int pos = cnt + __popc(mask & ((1u << lane) - 1u));
        if (a != 0.f && pos < KMAX) {
            g_cidx[m*KMAX + pos] = n;
            g_cval[m*KMAX + pos] = a * W1[n*NN + m];
        }
        cnt += __popc(mask);
    }
    if (lane == 0) g_clen[m] = min(cnt, KMAX);
    for (int f = lane; f < FF; f += 32) g_W2t[m*FF + f] = W2[f*NN + m];
}

// ---------------- K0b: pack tf32 B-fragments (ta slots use folded tkW3) ----------------
__device__ __forceinline__ float wsel2(const float* rk, int dt, int f, int n) {
    int c2 = f >> 2, s = f & 3;
    int cc = 2*c2 + (s & 1);
    if (s < 2) return g_tkW3[(dt*64 + cc)*64 + n];
    return rk[(dt*64 + cc)*64 + n];
}
__global__ void k0b_pack(const float* __restrict__ rk) {
    int kstep = blockIdx.x >> 3, nt = blockIdx.x & 7, lane = threadIdx.x;
    int dt = kstep >> 4, inner = kstep & 15;
    int f0 = inner*8 + (lane & 3);
    int n  = nt*8 + (lane >> 2);
    float w0 = wsel2(rk, dt, f0,     n);
    float w1 = wsel2(rk, dt, f0 + 4, n);
    float2 out;
    out.x = __uint_as_float(tf32r(w0));
    out.y = __uint_as_float(tf32r(w1));
    g_wfrag[(kstep*8 + nt)*32 + lane] = out;
}

// ---------------- K1: sparse graph attention -> nodef, per (b,t)  (R9 proven) ----------------
#define K1_SMEM (NN*FF*4)
__global__ void __launch_bounds__(512, 2)
k1_gc(const float* __restrict__ x, const float* __restrict__ b1) {
    extern __shared__ float sm[];
    float* xs = sm;
    int bt = blockIdx.x;
    int tid = threadIdx.x, lane = tid & 31, w = tid >> 5;

    const float4* xg  = (const float4*)(x + (size_t)bt*NN*FF);
    float4* xs4 = (float4*)xs;
    for (int i = tid; i < NN*FF/4; i += 512) xs4[i] = xg[i];
    __syncthreads();

    for (int m = w; m < NN; m += 16) {
        float f0 = 0.f, f1 = 0.f;
        int cl = g_clen[m];
        const int*   ci = g_cidx + m*KMAX;
        const float* cv = g_cval + m*KMAX;
        for (int k = 0; k < cl; k++) {
            int n = ci[k]; float v = cv[k];
            f0 += v * xs[n*64 + lane];
            f1 += v * xs[n*64 + lane + 32];
        }
        int rl = g_rlen[m];
        const int*   ri  = g_ridx + m*KMAX;
        const float* rmj = g_radj + m*KMAX;
        float lg0 = -3.0e38f, lg1 = -3.0e38f;
        for (int base = 0; base < rl; base += 8) {
            float pp[8];
            #pragma unroll
            for (int kk = 0; kk < 8; kk++) {
                int k = base + kk;
                if (k < rl) {
                    int j = ri[k];
                    pp[kk] = f0 * g_W2t[j*64 + lane] + f1 * g_W2t[j*64 + lane + 32];
                } else pp[kk] = 0.f;
            }
            float v = multi_reduce8(pp, lane);
            int k = base + (lane & 7);
            if (k < rl) {
                float val = v + b1[ri[k]] + rmj[k];
                if (k < 32) { if (lane == k)      lg0 = val; }
                else        { if (lane == k - 32) lg1 = val; }
            }
        }
        float mx = warp_max(fmaxf(lg0, lg1));
        float e0 = expf(lg0 - mx);
        float e1 = expf(lg1 - mx);
        float s  = warp_sum(e0 + e1);
        float inv = 1.f / s;
        float a0 = e0 * inv, a1 = e1 * inv;
        float n0 = 0.f, n1 = 0.f;
        for (int k = 0; k < rl; k++) {
            int j = ri[k];
            float wgt = (k < 32) ? __shfl_sync(0xffffffffu, a0, k)
                                 : __shfl_sync(0xffffffffu, a1, k - 32);
            n0 += wgt * xs[j*64 + lane];
            n1 += wgt * xs[j*64 + lane + 32];
        }
        size_t yo = ((size_t)bt*NN + m) * 64;
        g_nodef[yo + lane]      = n0;
        g_nodef[yo + lane + 32] = n1;
    }
}

// ---------------- K0v: w3v = W3@taW3; S1 = sum(taW1); sb = b2.taW3 (parallel) ----------------
__global__ void k0v_vec(const float* __restrict__ W3, const float* __restrict__ taW1,
                        const float* __restrict__ taW3, const float* __restrict__ b2) {
    __shared__ float red[64];
    int f = threadIdx.x;   // 64
    float acc = 0.f;
    #pragma unroll 4
    for (int c = 0; c < 64; c++) acc += W3[f*64 + c] * taW3[c];
    g_w3v[f] = acc;
    float s1 = 0.f;
    for (int n = f; n < NN; n += 64) s1 += taW1[n];
    red[f] = s1;
    __syncthreads();
    if (f < 32) red[f] += red[f + 32];
    __syncthreads();
    if (f == 0) {
        float t = 0.f;
        for (int i = 0; i < 32; i++) t += red[i];
        g_scal[0] = t;
    }
    __syncthreads();
    red[f] = b2[f] * taW3[f];
    __syncthreads();
    if (f < 32) red[f] += red[f + 32];
    __syncthreads();
    if (f == 0) {
        float t = 0.f;
        for (int i = 0; i < 32; i++) t += red[i];
        g_scal[1] = t;
    }
}

// ---------------- K0l: lhsW = W3@taW2 and lbias (block per n, smem-staged) ----------------
__global__ void __launch_bounds__(64)
k0l_fold(const float* __restrict__ W3, const float* __restrict__ taW2,
         const float* __restrict__ b2) {
    __shared__ float col[64];       // taW2[:, n]
    __shared__ float W3t[64*64];    // W3t[c*64 + f] = W3[f*64 + c]
    int n = blockIdx.x, f = threadIdx.x;
    col[f] = taW2[f*NN + n];
    for (int i = f; i < 64*64; i += 64) {
        int ff = i >> 6, cc = i & 63;
        W3t[cc*64 + ff] = W3[i];
    }
    __syncthreads();
    float acc = 0.f;
    #pragma unroll 4
    for (int c = 0; c < 64; c++) acc += W3t[c*64 + f] * col[c];
    g_lhsW[f*NN + n] = acc;
    if (f == 0) {
        float bsum = 0.f;
        #pragma unroll 4
        for (int c = 0; c < 64; c++) bsum += b2[c] * col[c];
        g_lbias[n] = g_scal[0] * bsum;
    }
}

// ---------------- K0bc1/2: conv bias from b2 ----------------
__global__ void k0bc1(const float* __restrict__ b2, const float* __restrict__ tk) {
    int dt = blockIdx.x, u = threadIdx.x;
    float acc = 0.f;
    #pragma unroll 4
    for (int c = 0; c < 64; c++) acc += b2[c] * tk[(dt*64 + c)*64 + u];
    g_tbias[dt*64 + u] = acc;
}
__global__ void k0bc2() {
    int t = blockIdx.x, u = threadIdx.x;
    float acc = 0.f;
    #pragma unroll
    for (int dt = 0; dt < KLEN; dt++) {
        int tin = t + dt - 5;
        if (tin >= 0 && tin < TT) acc += g_tbias[dt*64 + u];
    }
    g_bc[t*64 + u] = acc;
}

// ---------------- K2: r1f, rhs, lhs per (b,t) — folded maps ----------------
__global__ void __launch_bounds__(512, 2)
k2_ta(const float* __restrict__ taW1) {
    __shared__ float r1s[64];
    int bt = blockIdx.x;
    int tid = threadIdx.x, lane = tid & 31, w = tid >> 5;
    if (tid < 64) r1s[tid] = 0.f;
    __syncthreads();
    float w3a = g_w3v[lane], w3b = g_w3v[lane + 32];
    float sb  = g_scal[1];
    float r0 = 0.f, r1a = 0.f;
    const float* yb = g_nodef + (size_t)bt*NN*UU;
    for (int n = w; n < NN; n += 16) {
        float yv0 = yb[n*64 + lane], yv1 = yb[n*64 + lane + 32];
        float w1v = taW1[n];
        r0  += w1v * yv0;
        r1a += w1v * yv1;
        float p = warp_sum(yv0 * w3a + yv1 * w3b);
        if (lane == 0) g_rhs[bt*NN + n] = p + sb;
    }
    atomicAdd(&r1s[lane], r0);
    atomicAdd(&r1s[lane + 32], r1a);
    __syncthreads();
    for (int n = tid; n < NN; n += 512) {
        float acc = g_lbias[n];
        #pragma unroll
        for (int f = 0; f < 64; f++) acc += r1s[f] * g_lhsW[f*NN + n];
        g_lhs[bt*NN + n] = acc;
    }
}

// ---------------- K3a: product + sigmoid ----------------
#define K3A_SMEM ((TT*401 + 15*401) * 4)
__global__ void __launch_bounds__(512, 1)
k3a_prod(const float* __restrict__ be) {
    extern __shared__ float sm[];
    float* rs = sm;
    float* ls = sm + TT*401;
    int b = blockIdx.x >> 2, chunk = blockIdx.x & 3;
    int t0 = chunk * 15;
    int tid = threadIdx.x;
    for (int i = tid; i < TT*NN; i += 512) {
        int s = i / NN, n = i - s*NN;
        rs[s*401 + n] = g_rhs[(b*TT + s)*NN + n];
    }
    for (int i = tid; i < 15*NN; i += 512) {
        int r = i / NN, n = i - r*NN;
        ls[r*401 + n] = g_lhs[(b*TT + t0 + r)*NN + n];
    }
    __syncthreads();
    for (int p = tid; p < 15*TT; p += 512) {
        int r = p / TT, s2 = p - r*TT;
        float acc = 0.f;
        #pragma unroll 4
        for (int n = 0; n < NN; n++) acc += ls[r*401 + n] * rs[s2*401 + n];
        acc += be[(t0 + r)*TT + s2];
        g_sg[(b*TT + t0 + r)*TT + s2] = 1.f / (1.f + expf(-acc));
    }
}

// ---------------- K3b: E = Ve @ sg, softmax over axis -2 ----------------
__global__ void __launch_bounds__(512, 2)
k3b_soft(const float* __restrict__ Ve) {
    __shared__ float sgs[TT*TT];
    __shared__ float Es [TT*TT];
    int b = blockIdx.x, tid = threadIdx.x;
    for (int i = tid; i < TT*TT; i += 512) sgs[i] = g_sg[b*TT*TT + i];
    __syncthreads();
    for (int p = tid; p < TT*TT; p += 512) {
        int j = p / TT, l = p - j*TT;
        float acc = 0.f;
        #pragma unroll 4
        for (int k = 0; k < TT; k++) acc += Ve[j*TT + k] * sgs[k*TT + l];
        Es[p] = acc;
    }
    __syncthreads();
    if (tid < TT) {
        int l = tid;
        float mx = -3.0e38f;
        for (int j = 0; j < TT; j++) mx = fmaxf(mx, Es[j*TT + l]);
        float s = 0.f;
        for (int j = 0; j < TT; j++) s += expf(Es[j*TT + l] - mx);
        float inv = 1.f / s;
        for (int j = 0; j < TT; j++)
            g_ker[(b*TT + j)*TT + l] = expf(Es[j*TT + l] - mx) * inv;
    }
}

// ---------------- K4: 4 nodes/CTA, smem-staged B chunks, tf32 MMA ----------------
// M = 240 (+16 pad) rows, N = 64, K = 1536. 512 threads, occ 1.
// smem: az[300*132] + shared region (ysp 4*60*64 during phase 1, wbuf 4096 during phase 2).
#define K4_SHARED_REGION (NPC*TT*UU)            // 15360 floats >= wbuf 4096
#define K4_SMEM ((AZROWS*AZW + K4_SHARED_REGION) * 4)
__global__ void __launch_bounds__(512, 1)
k4_conv(const float* __restrict__ x,
        const float* __restrict__ tb, const float* __restrict__ rb,
        float* __restrict__ out) {
    extern __shared__ float sm[];
    float* az   = sm;                      // 300*132
    float* shr  = sm + AZROWS*AZW;         // ysp then wbuf
    int b  = blockIdx.x / (NN/NPC);
    int np = blockIdx.x - b*(NN/NPC);
    int n0 = np * NPC;
    int tid = threadIdx.x, lane = tid & 31, w = tid >> 5;
    const float* kerG = g_ker + b*TT*TT;

    // zero rows: per nn rows {0..4, 65..71} (12 each) + 12 dummy rows
    for (int i = tid; i < 60*AZW; i += 512) {
        int z = i / AZW, f = i - z*AZW;
        int row;
        if (z < 48) {
            int nn = z / 12, r = z % 12;
            row = nn*TPAD + ((r < 5) ? r : r + 60);
        } else {
            row = DROWS + (z - 48);
        }
        az[row*AZW + f] = 0.f;
    }
    // load nodef into ysp, x pairs into az x-slots (tf32)
    for (int i = tid; i < NPC*TT*32; i += 512) {
        int nn = i / (TT*32);
        int rr = i - nn*TT*32;
        int t  = rr >> 5, c2 = rr & 31;
        size_t gi = (((size_t)(b*TT + t))*NN + n0 + nn)*64 + 2*c2;
        *(float2*)(shr + (nn*TT + t)*64 + 2*c2) = *(const float2*)(g_nodef + gi);
        float2 xv = *(const float2*)(x + gi);
        uint2 xr;
        xr.x = tf32r(xv.x);
        xr.y = tf32r(xv.y);
        *(uint2*)(az + (nn*TPAD + t + 5)*AZW + c2*4 + 2) = xr;
    }
    __syncthreads();

    // ---- phase 1: taf[m][f-pair] = sum_t ker[t][m] * nodef[t][f-pair], tf32-rounded ----
    {
        int nn = w >> 2, mg = w & 3;       // 4 warps per node
        const float* yb = shr + nn*TT*64;
        for (int m = mg; m < TT; m += 4) {
            unsigned long long acc2 = 0ull;
            #pragma unroll 4
            for (int t = 0; t < TT; t++) {
                float kv = kerG[t*TT + m];
                unsigned long long yv = *(const unsigned long long*)(yb + t*64 + 2*lane);
                ffma2(acc2, packf2(kv, kv), yv);
            }
            float r0, r1; unpackf2(acc2, r0, r1);
            uint2 tr;
            tr.x = tf32r(r0);
            tr.y = tf32r(r1);
            *(uint2*)(az + (nn*TPAD + m + 5)*AZW + lane*4) = tr;
        }
    }
    __syncthreads();   // phase 1 done; shr region becomes wbuf

    // ---- phase 2: warp = 2 m-tiles x 4 n-tiles; B chunks staged in smem ----
    int p = w & 7, nhalf = w >> 3;
    int gr = lane >> 2, ctg = lane & 3;
    // 4 A-row pointers: rows 32p+gr+{0,8,16,24}
    const float* rp[4];
    int rnn[4], rtt[4]; bool rv[4];
    #pragma unroll
    for (int h = 0; h < 4; h++) {
        int ma = 32*p + 8*h + gr;
        bool v = (ma < NPC*TT);
        rv[h]  = v;
        rnn[h] = v ? (ma / TT) : 0;
        rtt[h] = v ? (ma % TT) : 0;
        rp[h]  = az + (v ? (rnn[h]*TPAD + rtt[h]) : DROWS) * AZW;
    }

    float acc[2][4][4];
    #pragma unroll
    for (int mm = 0; mm < 2; mm++)
        #pragma unroll
        for (int q = 0; q < 4; q++)
            #pragma unroll
            for (int i = 0; i < 4; i++) acc[mm][q][i] = 0.f;

    float2* wbuf = (float2*)shr;   // 2048 float2 = 8 inner x 8 nt x 32 lanes
    for (int dt = 0; dt < KLEN; dt++) {
        const float* r0p = rp[0] + dt*AZW;
        const float* r1p = rp[1] + dt*AZW;
        const float* r2p = rp[2] + dt*AZW;
        const float* r3p = rp[3] + dt*AZW;
        for (int half = 0; half < 2; half++) {
            // stage 16 KB weight chunk
            {
                const float4* src = (const float4*)(g_wfrag + (size_t)((dt*16 + half*8)*8)*32);
                float4* dst = (float4*)wbuf;
                dst[tid]       = src[tid];
                dst[tid + 512] = src[tid + 512];
            }
            __syncthreads();
            #pragma unroll
            for (int inner = 0; inner < 8; inner++) {
                int fo = (half*8 + inner)*8 + ctg;
                unsigned a00 = __float_as_uint(r0p[fo]);
                unsigned a02 = __float_as_uint(r0p[fo + 4]);
                unsigned a01 = __float_as_uint(r1p[fo]);
                unsigned a03 = __float_as_uint(r1p[fo + 4]);
                unsigned a10 = __float_as_uint(r2p[fo]);
                unsigned a12 = __float_as_uint(r2p[fo + 4]);
                unsigned a11 = __float_as_uint(r3p[fo]);
                unsigned a13 = __float_as_uint(r3p[fo + 4]);
                const float2* wi = wbuf + (size_t)inner*8*32 + lane;
                #pragma unroll
                for (int q = 0; q < 4; q++) {
                    float2 bv = wi[(nhalf*4 + q)*32];
                    unsigned b0 = __float_as_uint(bv.x);
                    unsigned b1 = __float_as_uint(bv.y);
                    mma_tf32(acc[0][q], a00, a01, a02, a03, b0, b1);
                    mma_tf32(acc[1][q], a10, a11, a12, a13, b0, b1);
                }
            }
            __syncthreads();
        }
    }

    // ---- epilogue: bias + softplus + store ----
    #pragma unroll
    for (int mm = 0; mm < 2; mm++) {
        int ha = 2*mm, hb = 2*mm + 1;
        #pragma unroll
        for (int q = 0; q < 4; q++) {
            int col = (nhalf*4 + q)*8 + 2*ctg;
            float tbc0 = tb[col]     + rb[col];
            float tbc1 = tb[col + 1] + rb[col + 1];
            if (rv[ha]) {
                size_t go = (((size_t)(b*TT + rtt[ha]))*NN + n0 + rnn[ha])*64 + col;
                float2 o;
                o.x = softplusf(acc[mm][q][0] + tbc0 + g_bc[rtt[ha]*64 + col]);
                o.y = softplusf(acc[mm][q][1] + tbc1 + g_bc[rtt[ha]*64 + col + 1]);
                *(float2*)(out + go) = o;
            }
            if (rv[hb]) {
                size_t go = (((size_t)(b*TT + rtt[hb]))*NN + n0 + rnn[hb])*64 + col;
                float2 o;
                o.x = softplusf(acc[mm][q][2] + tbc0 + g_bc[rtt[hb]*64 + col]);
                o.y = softplusf(acc[mm][q][3] + tbc1 + g_bc[rtt[hb]*64 + col + 1]);
                *(float2*)(out + go) = o;
            }
        }
    }
}

// ---------------- launch ----------------
extern "C" void kernel_launch(void* const* d_in, const int* in_sizes, int n_in,
                              void* d_out, int out_size) {
    const float* x    = (const float*)d_in[0];
    const float* A    = (const float*)d_in[1];
    const float* W1   = (const float*)d_in[2];
    const float* W2   = (const float*)d_in[3];
    const float* W3   = (const float*)d_in[4];
    const float* b1   = (const float*)d_in[5];
    const float* b2   = (const float*)d_in[6];
    const float* taW1 = (const float*)d_in[7];
    const float* taW2 = (const float*)d_in[8];
    const float* taW3 = (const float*)d_in[9];
    const float* Ve   = (const float*)d_in[10];
    const float* be   = (const float*)d_in[11];
    const float* tk   = (const float*)d_in[12];
    const float* tb   = (const float*)d_in[13];
    const float* rk   = (const float*)d_in[14];
    const float* rb   = (const float*)d_in[15];
    float* out = (float*)d_out;

    cudaFuncSetAttribute(k1_gc,    cudaFuncAttributeMaxDynamicSharedMemorySize, K1_SMEM);
    cudaFuncSetAttribute(k3a_prod, cudaFuncAttributeMaxDynamicSharedMemorySize, K3A_SMEM);
    cudaFuncSetAttribute(k4_conv,  cudaFuncAttributeMaxDynamicSharedMemorySize, K4_SMEM);

    k0w_fold<<<KLEN*64, 64>>>(tk, W3);          // 1
    k0_build<<<NN, 32>>>(A, W1, W2);            // 2
    k0b_pack<<<KSTEPS*8, 32>>>(rk);             // 3 (needs k0w)
    k1_gc<<<BT, 512, K1_SMEM>>>(x, b1);         // 4 <- profiled slot
    k0v_vec<<<1, 64>>>(W3, taW1, taW3, b2);     // 5
    k0l_fold<<<NN, 64>>>(W3, taW2, b2);         // 6 (needs k0v)
    k0bc1<<<KLEN, 64>>>(b2, tk);                // 7
    k0bc2<<<TT, 64>>>();                        // 8
    k2_ta<<<BT, 512>>>(taW1);                   // 9
    k3a_prod<<<BB*4, 512, K3A_SMEM>>>(be);
    k3b_soft<<<BB, 512>>>(Ve);
    k4_conv<<<BB*(NN/NPC), 512, K4_SMEM>>>(x, tb, rb, out);
}

// round 16
// speedup vs baseline: 1.1957x; 1.1957x over previous
#include <cuda_runtime.h>
#include <cuda_bf16.h>
#include <math.h>

// ---------------- problem constants ----------------
#define BB 8
#define TT 60
#define NN 400
#define FF 64
#define UU 64
#define KLEN 12
#define BT (BB*TT)        // 480
#define KMAX 64
#define TPAD 72           // az rows per node: row = t + dt, t in [0,60), dt in [0,12)
#define AZW 132           // az row stride in floats (132 % 32 == 4 -> conflict-free frags)
#define KSTEPS (KLEN*16)  // 192 k-steps of 8

// ---------------- device scratch (no runtime alloc allowed) ----------------
__device__ float g_W2t[NN*FF];        // W2t[j][f] = dgc_W2[f][j]
__device__ int   g_ridx[NN*KMAX];
__device__ float g_radj[NN*KMAX];
__device__ int   g_rlen[NN];
__device__ int   g_cidx[NN*KMAX];
__device__ float g_cval[NN*KMAX];
__device__ int   g_clen[NN];
__device__ float g_nodef[BT*NN*UU];   // attn @ x (pre-W3), ~49 MB
__device__ float g_lhs[BT*NN];
__device__ float g_rhs[BT*NN];
__device__ float g_sg [BB*TT*TT];
__device__ float g_ker[BB*TT*TT];
// W3-folded artifacts
__device__ float g_tkW3[KLEN*FF*UU];  // tkW3[dt][f][u] = sum_c W3[f][c]*tk[dt][c][u]
__device__ float g_w3v[UU];           // W3 @ taW3
__device__ float g_scal[2];           // [0]=sum(taW1), [1]=b2.taW3
__device__ float g_lbias[NN];         // S1 * (b2 @ taW2)
__device__ float g_lhsW[FF*NN];       // lhsW[f][n] = sum_c W3[f][c]*taW2[c][n]
__device__ float g_tbias[KLEN*UU];    // per-dt conv bias from b2
__device__ float g_bc[TT*UU];         // conv bias from b2 (edge-dependent)
// Pre-packed tf32 B-fragments: [(kstep*8 + nt)*32 + lane] = {B[k0+l%4][n], B[k0+4+l%4][n]}
__device__ float2 g_wfrag[KSTEPS*8*32];   // 393 KB

// ---------------- helpers ----------------
__device__ __forceinline__ unsigned long long packf2(float x, float y) {
    unsigned long long r;
    asm("mov.b64 %0, {%1, %2};" : "=l"(r) : "f"(x), "f"(y));
    return r;
}
__device__ __forceinline__ void unpackf2(unsigned long long v, float& x, float& y) {
    asm("mov.b64 {%0, %1}, %2;" : "=f"(x), "=f"(y) : "l"(v));
}
__device__ __forceinline__ void ffma2(unsigned long long& d, unsigned long long a, unsigned long long b) {
    asm("fma.rn.f32x2 %0, %1, %2, %0;" : "+l"(d) : "l"(a), "l"(b));
}
__device__ __forceinline__ unsigned tf32r(float x) {
    unsigned r; asm("cvt.rna.tf32.f32 %0, %1;" : "=r"(r) : "f"(x)); return r;
}
__device__ __forceinline__ void mma_tf32(float* c, unsigned a0, unsigned a1,
                                         unsigned a2, unsigned a3,
                                         unsigned b0, unsigned b1) {
    asm("mma.sync.aligned.m16n8k8.row.col.f32.tf32.tf32.f32 "
        "{%0,%1,%2,%3}, {%4,%5,%6,%7}, {%8,%9}, {%0,%1,%2,%3};"
        : "+f"(c[0]), "+f"(c[1]), "+f"(c[2]), "+f"(c[3])
        : "r"(a0), "r"(a1), "r"(a2), "r"(a3), "r"(b0), "r"(b1));
}
__device__ __forceinline__ float warp_sum(float v) {
    #pragma unroll
    for (int o = 16; o; o >>= 1) v += __shfl_xor_sync(0xffffffffu, v, o);
    return v;
}
__device__ __forceinline__ float warp_max(float v) {
    #pragma unroll
    for (int o = 16; o; o >>= 1) v = fmaxf(v, __shfl_xor_sync(0xffffffffu, v, o));
    return v;
}
// Reduce 8 per-lane partials across the warp in 9 SHFL.
__device__ __forceinline__ float multi_reduce8(const float* pp, int lane) {
    float q[4];
    bool b4 = (lane & 4) != 0;
    #pragma unroll
    for (int i = 0; i < 4; i++) {
        float send = b4 ? pp[i] : pp[i + 4];
        float recv = __shfl_xor_sync(0xffffffffu, send, 4);
        q[i] = (b4 ? pp[i + 4] : pp[i]) + recv;
    }
    float r[2];
    bool b2 = (lane & 2) != 0;
    #pragma unroll
    for (int i = 0; i < 2; i++) {
        float send = b2 ? q[i] : q[i + 2];
        float recv = __shfl_xor_sync(0xffffffffu, send, 2);
        r[i] = (b2 ? q[i + 2] : q[i]) + recv;
    }
    bool b1 = (lane & 1) != 0;
    float send = b1 ? r[0] : r[1];
    float recv = __shfl_xor_sync(0xffffffffu, send, 1);
    float v = (b1 ? r[1] : r[0]) + recv;
    v += __shfl_xor_sync(0xffffffffu, v, 8);
    v += __shfl_xor_sync(0xffffffffu, v, 16);
    return v;
}
__device__ __forceinline__ float softplusf(float z) {
    return fmaxf(z, 0.f) + log1pf(expf(-fabsf(z)));
}

// ---------------- K0w: fold W3 into tconv weights ----------------
__global__ void k0w_fold(const float* __restrict__ tk, const float* __restrict__ W3) {
    int dt = blockIdx.x >> 6, f = blockIdx.x & 63, u = threadIdx.x;
    float acc = 0.f;
    #pragma unroll 4
    for (int c = 0; c < 64; c++)
        acc += W3[f*64 + c] * tk[(dt*64 + c)*64 + u];
    g_tkW3[(dt*64 + f)*64 + u] = acc;
}

// ---------------- K0: CSR build + W2 transpose ----------------
__global__ void k0_build(const float* __restrict__ A, const float* __restrict__ W1,
                         const float* __restrict__ W2) {
    int m = blockIdx.x;
    int lane = threadIdx.x;
    int cnt = 0;
    for (int j0 = 0; j0 < NN; j0 += 32) {
        int j = j0 + lane;
        float a = (j < NN) ? A[m*NN + j] : 0.f;
        unsigned mask = __ballot_sync(0xffffffffu, a != 0.f);
        int pos = cnt + __popc(mask & ((1u << lane) - 1u));
        if (a != 0.f && pos < KMAX) {
            g_ridx[m*KMAX + pos] = j;
            g_radj[m*KMAX + pos] = -1e16f * (1.f - a);
        }
        cnt += __popc(mask);
    }
    if (lane == 0) g_rlen[m] = min(cnt, KMAX);
    cnt = 0;
    for (int n0 = 0; n0 < NN; n0 += 32) {
        int n = n0 + lane;
        float a = (n < NN) ? A[n*NN + m] : 0.f;
        unsigned mask = __ballot_sync(0xffffffffu, a != 0.f);
        int pos = cnt + __popc(mask & ((1u << lane) - 1u));
        if (a != 0.f && pos < KMAX) {
            g_cidx[m*KMAX + pos] = n;
            g_cval[m*KMAX + pos] = a * W1[n*NN + m];
        }
        cnt += __popc(mask);
    }
    if (lane == 0) g_clen[m] = min(cnt, KMAX);
    for (int f = lane; f < FF; f += 32) g_W2t[m*FF + f] = W2[f*NN + m];
}

// ---------------- K0b: pack tf32 B-fragments (ta slots use folded tkW3) ----------------
__device__ __forceinline__ float wsel2(const float* rk, int dt, int f, int n) {
    int c2 = f >> 2, s = f & 3;
    int cc = 2*c2 + (s & 1);
    if (s < 2) return g_tkW3[(dt*64 + cc)*64 + n];
    return rk[(dt*64 + cc)*64 + n];
}
__global__ void k0b_pack(const float* __restrict__ rk) {
    int kstep = blockIdx.x >> 3, nt = blockIdx.x & 7, lane = threadIdx.x;
    int dt = kstep >> 4, inner = kstep & 15;
    int f0 = inner*8 + (lane & 3);
    int n  = nt*8 + (lane >> 2);
    float w0 = wsel2(rk, dt, f0,     n);
    float w1 = wsel2(rk, dt, f0 + 4, n);
    float2 out;
    out.x = __uint_as_float(tf32r(w0));
    out.y = __uint_as_float(tf32r(w1));
    g_wfrag[(kstep*8 + nt)*32 + lane] = out;
}

// ---------------- K1: sparse graph attention -> nodef, per (b,t)  (R9 proven) ----------------
#define K1_SMEM (NN*FF*4)
__global__ void __launch_bounds__(512, 2)
k1_gc(const float* __restrict__ x, const float* __restrict__ b1) {
    extern __shared__ float sm[];
    float* xs = sm;
    int bt = blockIdx.x;
    int tid = threadIdx.x, lane = tid & 31, w = tid >> 5;

    const float4* xg  = (const float4*)(x + (size_t)bt*NN*FF);
    float4* xs4 = (float4*)xs;
    for (int i = tid; i < NN*FF/4; i += 512) xs4[i] = xg[i];
    __syncthreads();

    for (int m = w; m < NN; m += 16) {
        float f0 = 0.f, f1 = 0.f;
        int cl = g_clen[m];
        const int*   ci = g_cidx + m*KMAX;
        const float* cv = g_cval + m*KMAX;
        for (int k = 0; k < cl; k++) {
            int n = ci[k]; float v = cv[k];
            f0 += v * xs[n*64 + lane];
            f1 += v * xs[n*64 + lane + 32];
        }
        int rl = g_rlen[m];
        const int*   ri  = g_ridx + m*KMAX;
        const float* rmj = g_radj + m*KMAX;
        float lg0 = -3.0e38f, lg1 = -3.0e38f;
        for (int base = 0; base < rl; base += 8) {
            float pp[8];
            #pragma unroll
            for (int kk = 0; kk < 8; kk++) {
                int k = base + kk;
                if (k < rl) {
                    int j = ri[k];
                    pp[kk] = f0 * g_W2t[j*64 + lane] + f1 * g_W2t[j*64 + lane + 32];
                } else pp[kk] = 0.f;
            }
            float v = multi_reduce8(pp, lane);
            int k = base + (lane & 7);
            if (k < rl) {
                float val = v + b1[ri[k]] + rmj[k];
                if (k < 32) { if (lane == k)      lg0 = val; }
                else        { if (lane == k - 32) lg1 = val; }
            }
        }
        float mx = warp_max(fmaxf(lg0, lg1));
        float e0 = expf(lg0 - mx);
        float e1 = expf(lg1 - mx);
        float s  = warp_sum(e0 + e1);
        float inv = 1.f / s;
        float a0 = e0 * inv, a1 = e1 * inv;
        float n0 = 0.f, n1 = 0.f;
        for (int k = 0; k < rl; k++) {
            int j = ri[k];
            float wgt = (k < 32) ? __shfl_sync(0xffffffffu, a0, k)
                                 : __shfl_sync(0xffffffffu, a1, k - 32);
            n0 += wgt * xs[j*64 + lane];
            n1 += wgt * xs[j*64 + lane + 32];
        }
        size_t yo = ((size_t)bt*NN + m) * 64;
        g_nodef[yo + lane]      = n0;
        g_nodef[yo + lane + 32] = n1;
    }
}

// ---------------- K0v: w3v = W3@taW3; S1 = sum(taW1); sb = b2.taW3 (parallel) ----------------
__global__ void k0v_vec(const float* __restrict__ W3, const float* __restrict__ taW1,
                        const float* __restrict__ taW3, const float* __restrict__ b2) {
    __shared__ float red[64];
    int f = threadIdx.x;   // 64
    float acc = 0.f;
    #pragma unroll 4
    for (int c = 0; c < 64; c++) acc += W3[f*64 + c] * taW3[c];
    g_w3v[f] = acc;
    float s1 = 0.f;
    for (int n = f; n < NN; n += 64) s1 += taW1[n];
    red[f] = s1;
    __syncthreads();
    if (f < 32) red[f] += red[f + 32];
    __syncthreads();
    if (f == 0) {
        float t = 0.f;
        for (int i = 0; i < 32; i++) t += red[i];
        g_scal[0] = t;
    }
    __syncthreads();
    red[f] = b2[f] * taW3[f];
    __syncthreads();
    if (f < 32) red[f] += red[f + 32];
    __syncthreads();
    if (f == 0) {
        float t = 0.f;
        for (int i = 0; i < 32; i++) t += red[i];
        g_scal[1] = t;
    }
}

// ---------------- K0l: lhsW = W3@taW2 and lbias (block per n, smem-staged) ----------------
__global__ void __launch_bounds__(64)
k0l_fold(const float* __restrict__ W3, const float* __restrict__ taW2,
         const float* __restrict__ b2) {
    __shared__ float col[64];       // taW2[:, n]
    __shared__ float W3t[64*64];    // W3t[c*64 + f] = W3[f*64 + c]
    int n = blockIdx.x, f = threadIdx.x;
    col[f] = taW2[f*NN + n];
    for (int i = f; i < 64*64; i += 64) {
        int ff = i >> 6, cc = i & 63;
        W3t[cc*64 + ff] = W3[i];
    }
    __syncthreads();
    float acc = 0.f;
    #pragma unroll 4
    for (int c = 0; c < 64; c++) acc += W3t[c*64 + f] * col[c];
    g_lhsW[f*NN + n] = acc;
    if (f == 0) {
        float bsum = 0.f;
        #pragma unroll 4
        for (int c = 0; c < 64; c++) bsum += b2[c] * col[c];
        g_lbias[n] = g_scal[0] * bsum;
    }
}

// ---------------- K0bc1/2: conv bias from b2 ----------------
__global__ void k0bc1(const float* __restrict__ b2, const float* __restrict__ tk) {
    int dt = blockIdx.x, u = threadIdx.x;
    float acc = 0.f;
    #pragma unroll 4
    for (int c = 0; c < 64; c++) acc += b2[c] * tk[(dt*64 + c)*64 + u];
    g_tbias[dt*64 + u] = acc;
}
__global__ void k0bc2() {
    int t = blockIdx.x, u = threadIdx.x;
    float acc = 0.f;
    #pragma unroll
    for (int dt = 0; dt < KLEN; dt++) {
        int tin = t + dt - 5;
        if (tin >= 0 && tin < TT) acc += g_tbias[dt*64 + u];
    }
    g_bc[t*64 + u] = acc;
}

// ---------------- K2: r1f, rhs, lhs per (b,t) — folded maps ----------------
__global__ void __launch_bounds__(512, 2)
k2_ta(const float* __restrict__ taW1) {
    __shared__ float r1s[64];
    int bt = blockIdx.x;
    int tid = threadIdx.x, lane = tid & 31, w = tid >> 5;
    if (tid < 64) r1s[tid] = 0.f;
    __syncthreads();
    float w3a = g_w3v[lane], w3b = g_w3v[lane + 32];
    float sb  = g_scal[1];
    float r0 = 0.f, r1a = 0.f;
    const float* yb = g_nodef + (size_t)bt*NN*UU;
    for (int n = w; n < NN; n += 16) {
        float yv0 = yb[n*64 + lane], yv1 = yb[n*64 + lane + 32];
        float w1v = taW1[n];
        r0  += w1v * yv0;
        r1a += w1v * yv1;
        float p = warp_sum(yv0 * w3a + yv1 * w3b);
        if (lane == 0) g_rhs[bt*NN + n] = p + sb;
    }
    atomicAdd(&r1s[lane], r0);
    atomicAdd(&r1s[lane + 32], r1a);
    __syncthreads();
    for (int n = tid; n < NN; n += 512) {
        float acc = g_lbias[n];
        #pragma unroll
        for (int f = 0; f < 64; f++) acc += r1s[f] * g_lhsW[f*NN + n];
        g_lhs[bt*NN + n] = acc;
    }
}

// ---------------- K3a: product + sigmoid ----------------
#define K3A_SMEM ((TT*401 + 15*401) * 4)
__global__ void __launch_bounds__(512, 1)
k3a_prod(const float* __restrict__ be) {
    extern __shared__ float sm[];
    float* rs = sm;
    float* ls = sm + TT*401;
    int b = blockIdx.x >> 2, chunk = blockIdx.x & 3;
    int t0 = chunk * 15;
    int tid = threadIdx.x;
    for (int i = tid; i < TT*NN; i += 512) {
        int s = i / NN, n = i - s*NN;
        rs[s*401 + n] = g_rhs[(b*TT + s)*NN + n];
    }
    for (int i = tid; i < 15*NN; i += 512) {
        int r = i / NN, n = i - r*NN;
        ls[r*401 + n] = g_lhs[(b*TT + t0 + r)*NN + n];
    }
    __syncthreads();
    for (int p = tid; p < 15*TT; p += 512) {
        int r = p / TT, s2 = p - r*TT;
        float acc = 0.f;
        #pragma unroll 4
        for (int n = 0; n < NN; n++) acc += ls[r*401 + n] * rs[s2*401 + n];
        acc += be[(t0 + r)*TT + s2];
        g_sg[(b*TT + t0 + r)*TT + s2] = 1.f / (1.f + expf(-acc));
    }
}

// ---------------- K3b: E = Ve @ sg, softmax over axis -2 ----------------
__global__ void __launch_bounds__(512, 2)
k3b_soft(const float* __restrict__ Ve) {
    __shared__ float sgs[TT*TT];
    __shared__ float Es [TT*TT];
    int b = blockIdx.x, tid = threadIdx.x;
    for (int i = tid; i < TT*TT; i += 512) sgs[i] = g_sg[b*TT*TT + i];
    __syncthreads();
    for (int p = tid; p < TT*TT; p += 512) {
        int j = p / TT, l = p - j*TT;
        float acc = 0.f;
        #pragma unroll 4
        for (int k = 0; k < TT; k++) acc += Ve[j*TT + k] * sgs[k*TT + l];
        Es[p] = acc;
    }
    __syncthreads();
    if (tid < TT) {
        int l = tid;
        float mx = -3.0e38f;
        for (int j = 0; j < TT; j++) mx = fmaxf(mx, Es[j*TT + l]);
        float s = 0.f;
        for (int j = 0; j < TT; j++) s += expf(Es[j*TT + l] - mx);
        float inv = 1.f / s;
        for (int j = 0; j < TT; j++)
            g_ker[(b*TT + j)*TT + l] = expf(Es[j*TT + l] - mx) * inv;
    }
}

// ---------------- K4: (ker·nodef | x) GEMM, R14 structure + per-dt warp phase-lock ----------------
// 2 nodes/CTA, 512 threads, 2 CTAs/SM. B-fragment stream kept L1-resident by
// syncing all warps at each dt boundary (32 KB window/CTA, 64 KB/SM < L1).
#define AZROWS (2*TPAD + 12)
#define K4_SMEM ((2*TT*UU + AZROWS*AZW) * 4)
__global__ void __launch_bounds__(512, 2)
k4_conv(const float* __restrict__ x,
        const float* __restrict__ tb, const float* __restrict__ rb,
        float* __restrict__ out) {
    extern __shared__ float sm[];
    float* ysp = sm;                      // 7680 (nodef staging)
    float* az  = sm + 2*TT*UU;            // AZROWS*AZW
    int b  = blockIdx.x / (NN/2);
    int np = blockIdx.x - b*(NN/2);
    int n0 = np * 2;
    int tid = threadIdx.x, lane = tid & 31, w = tid >> 5;
    const float* kerG = g_ker + b*TT*TT;

    for (int i = tid; i < 36*AZW; i += 512) {
        int z = i / AZW, f = i - z*AZW;
        int row;
        if (z < 24) {
            int nn = z / 12, r = z % 12;
            row = nn*TPAD + ((r < 5) ? r : r + 60);
        } else {
            row = 2*TPAD + (z - 24);
        }
        az[row*AZW + f] = 0.f;
    }
    for (int i = tid; i < 2*TT*32; i += 512) {
        int nn = i / (TT*32);
        int rr = i - nn*TT*32;
        int t  = rr >> 5, c2 = rr & 31;
        size_t gi = (((size_t)(b*TT + t))*NN + n0 + nn)*64 + 2*c2;
        *(float2*)(ysp + (nn*TT + t)*64 + 2*c2) = *(const float2*)(g_nodef + gi);
        float2 xv = *(const float2*)(x + gi);
        uint2 xr;
        xr.x = tf32r(xv.x);
        xr.y = tf32r(xv.y);
        *(uint2*)(az + (nn*TPAD + t + 5)*AZW + c2*4 + 2) = xr;
    }
    __syncthreads();

    // ---- phase 1: taf[m][f-pair] = sum_t ker[t][m] * nodef[t][f-pair], tf32-rounded ----
    {
        int nn = w >> 3, mg = w & 7;
        const float* yb = ysp + nn*TT*64;
        for (int m = mg; m < TT; m += 8) {
            unsigned long long acc2 = 0ull;
            #pragma unroll 4
            for (int t = 0; t < TT; t++) {
                float kv = kerG[t*TT + m];
                unsigned long long yv = *(const unsigned long long*)(yb + t*64 + 2*lane);
                ffma2(acc2, packf2(kv, kv), yv);
            }
            float r0, r1; unpackf2(acc2, r0, r1);
            uint2 tr;
            tr.x = tf32r(r0);
            tr.y = tf32r(r1);
            *(uint2*)(az + (nn*TPAD + m + 5)*AZW + lane*4) = tr;
        }
    }
    __syncthreads();

    // ---- phase 2: D[m, n] = A[m, :] @ W via m16n8k8 tf32 MMA ----
    int mt = w & 7, nhalf = w >> 3;
    int gr = lane >> 2, ctg = lane & 3;
    int ma = mt*16 + gr, mb = ma + 8;
    bool va = (ma < 120), vb = (mb < 120);
    int nna = va ? (ma / 60) : 0,  tta = va ? (ma % 60) : 0;
    int nnb = vb ? (mb / 60) : 0,  ttb = vb ? (mb % 60) : 0;
    const float* pa = az + (va ? (nna*TPAD + tta) : 2*TPAD) * AZW;
    const float* pb = az + (vb ? (nnb*TPAD + ttb) : 2*TPAD) * AZW;

    float acc[4][4];
    #pragma unroll
    for (int q = 0; q < 4; q++)
        #pragma unroll
        for (int i = 0; i < 4; i++) acc[q][i] = 0.f;

    for (int dt = 0; dt < KLEN; dt++) {
        __syncthreads();   // phase-lock all warps into the same 32 KB B window (L1-resident)
        const float* ra = pa + dt*AZW;
        const float* rb2 = pb + dt*AZW;
        const float2* wf = g_wfrag + ((size_t)(dt*16))*8*32;
        #pragma unroll 4
        for (int inner = 0; inner < 16; inner++) {
            int fo = inner*8 + ctg;
            unsigned a0 = __float_as_uint(ra[fo]);
            unsigned a2 = __float_as_uint(ra[fo + 4]);
            unsigned a1 = __float_as_uint(rb2[fo]);
            unsigned a3 = __float_as_uint(rb2[fo + 4]);
            const float2* wi = wf + inner*8*32 + lane;
            #pragma unroll
            for (int q = 0; q < 4; q++) {
                int nt = nhalf*4 + q;
                float2 bv = wi[nt*32];
                mma_tf32(acc[q], a0, a1, a2, a3,
                         __float_as_uint(bv.x), __float_as_uint(bv.y));
            }
        }
    }

    // ---- epilogue: bias (incl. folded-b2 conv bias) + softplus + store ----
    #pragma unroll
    for (int q = 0; q < 4; q++) {
        int col = (nhalf*4 + q)*8 + 2*ctg;
        float tbc0 = tb[col]     + rb[col];
        float tbc1 = tb[col + 1] + rb[col + 1];
        if (va) {
            size_t go = (((size_t)(b*TT + tta))*NN + n0 + nna)*64 + col;
            float2 o;
            o.x = softplusf(acc[q][0] + tbc0 + g_bc[tta*64 + col]);
            o.y = softplusf(acc[q][1] + tbc1 + g_bc[tta*64 + col + 1]);
            *(float2*)(out + go) = o;
        }
        if (vb) {
            size_t go = (((size_t)(b*TT + ttb))*NN + n0 + nnb)*64 + col;
            float2 o;
            o.x = softplusf(acc[q][2] + tbc0 + g_bc[ttb*64 + col]);
            o.y = softplusf(acc[q][3] + tbc1 + g_bc[ttb*64 + col + 1]);
            *(float2*)(out + go) = o;
        }
    }
}

// ---------------- launch ----------------
extern "C" void kernel_launch(void* const* d_in, const int* in_sizes, int n_in,
                              void* d_out, int out_size) {
    const float* x    = (const float*)d_in[0];
    const float* A    = (const float*)d_in[1];
    const float* W1   = (const float*)d_in[2];
    const float* W2   = (const float*)d_in[3];
    const float* W3   = (const float*)d_in[4];
    const float* b1   = (const float*)d_in[5];
    const float* b2   = (const float*)d_in[6];
    const float* taW1 = (const float*)d_in[7];
    const float* taW2 = (const float*)d_in[8];
    const float* taW3 = (const float*)d_in[9];
    const float* Ve   = (const float*)d_in[10];
    const float* be   = (const float*)d_in[11];
    const float* tk   = (const float*)d_in[12];
    const float* tb   = (const float*)d_in[13];
    const float* rk   = (const float*)d_in[14];
    const float* rb   = (const float*)d_in[15];
    float* out = (float*)d_out;

    cudaFuncSetAttribute(k1_gc,    cudaFuncAttributeMaxDynamicSharedMemorySize, K1_SMEM);
    cudaFuncSetAttribute(k3a_prod, cudaFuncAttributeMaxDynamicSharedMemorySize, K3A_SMEM);
    cudaFuncSetAttribute(k4_conv,  cudaFuncAttributeMaxDynamicSharedMemorySize, K4_SMEM);

    k0w_fold<<<KLEN*64, 64>>>(tk, W3);          // 1
    k0_build<<<NN, 32>>>(A, W1, W2);            // 2
    k0b_pack<<<KSTEPS*8, 32>>>(rk);             // 3 (needs k0w)
    k1_gc<<<BT, 512, K1_SMEM>>>(x, b1);         // 4 <- profiled slot
    k0v_vec<<<1, 64>>>(W3, taW1, taW3, b2);     // 5
    k0l_fold<<<NN, 64>>>(W3, taW2, b2);         // 6 (needs k0v)
    k0bc1<<<KLEN, 64>>>(b2, tk);                // 7
    k0bc2<<<TT, 64>>>();                        // 8
    k2_ta<<<BT, 512>>>(taW1);                   // 9
    k3a_prod<<<BB*4, 512, K3A_SMEM>>>(be);
    k3b_soft<<<BB, 512>>>(Ve);
    k4_conv<<<BB*(NN/2), 512, K4_SMEM>>>(x, tb, rb, out);
}

// round 17
// speedup vs baseline: 1.2383x; 1.0356x over previous
#include <cuda_runtime.h>
#include <cuda_bf16.h>
#include <math.h>

// ---------------- problem constants ----------------
#define BB 8
#define TT 60
#define NN 400
#define FF 64
#define UU 64
#define KLEN 12
#define BT (BB*TT)        // 480
#define KMAX 64
#define TPAD 72           // az rows per node: row = t + dt, t in [0,60), dt in [0,12)
#define AZW 132           // az row stride in floats (132 % 32 == 4 -> conflict-free frags)
#define KSTEPS (KLEN*16)  // 192 k-steps of 8

// ---------------- device scratch (no runtime alloc allowed) ----------------
__device__ float g_W2t[NN*FF];        // W2t[j][f] = dgc_W2[f][j]
__device__ int   g_ridx[NN*KMAX];
__device__ float g_radj[NN*KMAX];
__device__ int   g_rlen[NN];
__device__ int   g_cidx[NN*KMAX];
__device__ float g_cval[NN*KMAX];
__device__ int   g_clen[NN];
__device__ float g_nodef[BT*NN*UU];   // attn @ x (pre-W3), ~49 MB
__device__ float g_lhs[BT*NN];
__device__ float g_rhs[BT*NN];
__device__ float g_sg [BB*TT*TT];
__device__ float g_ker[BB*TT*TT];
// W3-folded artifacts
__device__ float g_tkW3[KLEN*FF*UU];  // tkW3[dt][f][u] = sum_c W3[f][c]*tk[dt][c][u]
__device__ float g_w3v[UU];           // W3 @ taW3
__device__ float g_scal[2];           // [0]=sum(taW1), [1]=b2.taW3
__device__ float g_lbias[NN];         // S1 * (b2 @ taW2)
__device__ float g_lhsW[FF*NN];       // lhsW[f][n] = sum_c W3[f][c]*taW2[c][n]
__device__ float g_tbias[KLEN*UU];    // per-dt conv bias from b2
__device__ float g_bc[TT*UU];         // conv bias from b2 (edge-dependent)
// Pre-packed tf32 B-fragments: [(kstep*8 + nt)*32 + lane] = {B[k0+l%4][n], B[k0+4+l%4][n]}
__device__ float2 g_wfrag[KSTEPS*8*32];   // 393 KB

// ---------------- helpers ----------------
__device__ __forceinline__ unsigned long long packf2(float x, float y) {
    unsigned long long r;
    asm("mov.b64 %0, {%1, %2};" : "=l"(r) : "f"(x), "f"(y));
    return r;
}
__device__ __forceinline__ void unpackf2(unsigned long long v, float& x, float& y) {
    asm("mov.b64 {%0, %1}, %2;" : "=f"(x), "=f"(y) : "l"(v));
}
__device__ __forceinline__ void ffma2(unsigned long long& d, unsigned long long a, unsigned long long b) {
    asm("fma.rn.f32x2 %0, %1, %2, %0;" : "+l"(d) : "l"(a), "l"(b));
}
__device__ __forceinline__ unsigned tf32r(float x) {
    unsigned r; asm("cvt.rna.tf32.f32 %0, %1;" : "=r"(r) : "f"(x)); return r;
}
__device__ __forceinline__ void mma_tf32(float* c, unsigned a0, unsigned a1,
                                         unsigned a2, unsigned a3,
                                         unsigned b0, unsigned b1) {
    asm("mma.sync.aligned.m16n8k8.row.col.f32.tf32.tf32.f32 "
        "{%0,%1,%2,%3}, {%4,%5,%6,%7}, {%8,%9}, {%0,%1,%2,%3};"
        : "+f"(c[0]), "+f"(c[1]), "+f"(c[2]), "+f"(c[3])
        : "r"(a0), "r"(a1), "r"(a2), "r"(a3), "r"(b0), "r"(b1));
}
__device__ __forceinline__ float warp_sum(float v) {
    #pragma unroll
    for (int o = 16; o; o >>= 1) v += __shfl_xor_sync(0xffffffffu, v, o);
    return v;
}
__device__ __forceinline__ float warp_max(float v) {
    #pragma unroll
    for (int o = 16; o; o >>= 1) v = fmaxf(v, __shfl_xor_sync(0xffffffffu, v, o));
    return v;
}
// Reduce 8 per-lane partials across the warp in 9 SHFL.
__device__ __forceinline__ float multi_reduce8(const float* pp, int lane) {
    float q[4];
    bool b4 = (lane & 4) != 0;
    #pragma unroll
    for (int i = 0; i < 4; i++) {
        float send = b4 ? pp[i] : pp[i + 4];
        float recv = __shfl_xor_sync(0xffffffffu, send, 4);
        q[i] = (b4 ? pp[i + 4] : pp[i]) + recv;
    }
    float r[2];
    bool b2 = (lane & 2) != 0;
    #pragma unroll
    for (int i = 0; i < 2; i++) {
        float send = b2 ? q[i] : q[i + 2];
        float recv = __shfl_xor_sync(0xffffffffu, send, 2);
        r[i] = (b2 ? q[i + 2] : q[i]) + recv;
    }
    bool b1 = (lane & 1) != 0;
    float send = b1 ? r[0] : r[1];
    float recv = __shfl_xor_sync(0xffffffffu, send, 1);
    float v = (b1 ? r[1] : r[0]) + recv;
    v += __shfl_xor_sync(0xffffffffu, v, 8);
    v += __shfl_xor_sync(0xffffffffu, v, 16);
    return v;
}
__device__ __forceinline__ float softplusf(float z) {
    return fmaxf(z, 0.f) + log1pf(expf(-fabsf(z)));
}

// ---------------- K0w: fold W3 into tconv weights ----------------
__global__ void k0w_fold(const float* __restrict__ tk, const float* __restrict__ W3) {
    int dt = blockIdx.x >> 6, f = blockIdx.x & 63, u = threadIdx.x;
    float acc = 0.f;
    #pragma unroll 4
    for (int c = 0; c < 64; c++)
        acc += W3[f*64 + c] * tk[(dt*64 + c)*64 + u];
    g_tkW3[(dt*64 + f)*64 + u] = acc;
}

// ---------------- K0: CSR build + W2 transpose ----------------
__global__ void k0_build(const float* __restrict__ A, const float* __restrict__ W1,
                         const float* __restrict__ W2) {
    int m = blockIdx.x;
    int lane = threadIdx.x;
    int cnt = 0;
    for (int j0 = 0; j0 < NN; j0 += 32) {
        int j = j0 + lane;
        float a = (j < NN) ? A[m*NN + j] : 0.f;
        unsigned mask = __ballot_sync(0xffffffffu, a != 0.f);
        int pos = cnt + __popc(mask & ((1u << lane) - 1u));
        if (a != 0.f && pos < KMAX) {
            g_ridx[m*KMAX + pos] = j;
            g_radj[m*KMAX + pos] = -1e16f * (1.f - a);
        }
        cnt += __popc(mask);
    }
    if (lane == 0) g_rlen[m] = min(cnt, KMAX);
    cnt = 0;
    for (int n0 = 0; n0 < NN; n0 += 32) {
        int n = n0 + lane;
        float a = (n < NN) ? A[n*NN + m] : 0.f;
        unsigned mask = __ballot_sync(0xffffffffu, a != 0.f);
        int pos = cnt + __popc(mask & ((1u << lane) - 1u));
        if (a != 0.f && pos < KMAX) {
            g_cidx[m*KMAX + pos] = n;
            g_cval[m*KMAX + pos] = a * W1[n*NN + m];
        }
        cnt += __popc(mask);
    }
    if (lane == 0) g_clen[m] = min(cnt, KMAX);
    for (int f = lane; f < FF; f += 32) g_W2t[m*FF + f] = W2[f*NN + m];
}

// ---------------- K0b: pack tf32 B-fragments (ta slots use folded tkW3) ----------------
__device__ __forceinline__ float wsel2(const float* rk, int dt, int f, int n) {
    int c2 = f >> 2, s = f & 3;
    int cc = 2*c2 + (s & 1);
    if (s < 2) return g_tkW3[(dt*64 + cc)*64 + n];
    return rk[(dt*64 + cc)*64 + n];
}
__global__ void k0b_pack(const float* __restrict__ rk) {
    int kstep = blockIdx.x >> 3, nt = blockIdx.x & 7, lane = threadIdx.x;
    int dt = kstep >> 4, inner = kstep & 15;
    int f0 = inner*8 + (lane & 3);
    int n  = nt*8 + (lane >> 2);
    float w0 = wsel2(rk, dt, f0,     n);
    float w1 = wsel2(rk, dt, f0 + 4, n);
    float2 out;
    out.x = __uint_as_float(tf32r(w0));
    out.y = __uint_as_float(tf32r(w1));
    g_wfrag[(kstep*8 + nt)*32 + lane] = out;
}

// ---------------- K1: sparse graph attention -> nodef, per (b,t)  (R9 proven) ----------------
#define K1_SMEM (NN*FF*4)
__global__ void __launch_bounds__(512, 2)
k1_gc(const float* __restrict__ x, const float* __restrict__ b1) {
    extern __shared__ float sm[];
    float* xs = sm;
    int bt = blockIdx.x;
    int tid = threadIdx.x, lane = tid & 31, w = tid >> 5;

    const float4* xg  = (const float4*)(x + (size_t)bt*NN*FF);
    float4* xs4 = (float4*)xs;
    for (int i = tid; i < NN*FF/4; i += 512) xs4[i] = xg[i];
    __syncthreads();

    for (int m = w; m < NN; m += 16) {
        float f0 = 0.f, f1 = 0.f;
        int cl = g_clen[m];
        const int*   ci = g_cidx + m*KMAX;
        const float* cv = g_cval + m*KMAX;
        for (int k = 0; k < cl; k++) {
            int n = ci[k]; float v = cv[k];
            f0 += v * xs[n*64 + lane];
            f1 += v * xs[n*64 + lane + 32];
        }
        int rl = g_rlen[m];
        const int*   ri  = g_ridx + m*KMAX;
        const float* rmj = g_radj + m*KMAX;
        float lg0 = -3.0e38f, lg1 = -3.0e38f;
        for (int base = 0; base < rl; base += 8) {
            float pp[8];
            #pragma unroll
            for (int kk = 0; kk < 8; kk++) {
                int k = base + kk;
                if (k < rl) {
                    int j = ri[k];
                    pp[kk] = f0 * g_W2t[j*64 + lane] + f1 * g_W2t[j*64 + lane + 32];
                } else pp[kk] = 0.f;
            }
            float v = multi_reduce8(pp, lane);
            int k = base + (lane & 7);
            if (k < rl) {
                float val = v + b1[ri[k]] + rmj[k];
                if (k < 32) { if (lane == k)      lg0 = val; }
                else        { if (lane == k - 32) lg1 = val; }
            }
        }
        float mx = warp_max(fmaxf(lg0, lg1));
        float e0 = expf(lg0 - mx);
        float e1 = expf(lg1 - mx);
        float s  = warp_sum(e0 + e1);
        float inv = 1.f / s;
        float a0 = e0 * inv, a1 = e1 * inv;
        float n0 = 0.f, n1 = 0.f;
        for (int k = 0; k < rl; k++) {
            int j = ri[k];
            float wgt = (k < 32) ? __shfl_sync(0xffffffffu, a0, k)
                                 : __shfl_sync(0xffffffffu, a1, k - 32);
            n0 += wgt * xs[j*64 + lane];
            n1 += wgt * xs[j*64 + lane + 32];
        }
        size_t yo = ((size_t)bt*NN + m) * 64;
        g_nodef[yo + lane]      = n0;
        g_nodef[yo + lane + 32] = n1;
    }
}

// ---------------- K0v: w3v = W3@taW3; S1 = sum(taW1); sb = b2.taW3 (parallel) ----------------
__global__ void k0v_vec(const float* __restrict__ W3, const float* __restrict__ taW1,
                        const float* __restrict__ taW3, const float* __restrict__ b2) {
    __shared__ float red[64];
    int f = threadIdx.x;   // 64
    float acc = 0.f;
    #pragma unroll 4
    for (int c = 0; c < 64; c++) acc += W3[f*64 + c] * taW3[c];
    g_w3v[f] = acc;
    float s1 = 0.f;
    for (int n = f; n < NN; n += 64) s1 += taW1[n];
    red[f] = s1;
    __syncthreads();
    if (f < 32) red[f] += red[f + 32];
    __syncthreads();
    if (f == 0) {
        float t = 0.f;
        for (int i = 0; i < 32; i++) t += red[i];
        g_scal[0] = t;
    }
    __syncthreads();
    red[f] = b2[f] * taW3[f];
    __syncthreads();
    if (f < 32) red[f] += red[f + 32];
    __syncthreads();
    if (f == 0) {
        float t = 0.f;
        for (int i = 0; i < 32; i++) t += red[i];
        g_scal[1] = t;
    }
}

// ---------------- K0l: lhsW = W3@taW2 and lbias (block per n, smem-staged) ----------------
__global__ void __launch_bounds__(64)
k0l_fold(const float* __restrict__ W3, const float* __restrict__ taW2,
         const float* __restrict__ b2) {
    __shared__ float col[64];       // taW2[:, n]
    __shared__ float W3t[64*64];    // W3t[c*64 + f] = W3[f*64 + c]
    int n = blockIdx.x, f = threadIdx.x;
    col[f] = taW2[f*NN + n];
    for (int i = f; i < 64*64; i += 64) {
        int ff = i >> 6, cc = i & 63;
        W3t[cc*64 + ff] = W3[i];
    }
    __syncthreads();
    float acc = 0.f;
    #pragma unroll 4
    for (int c = 0; c < 64; c++) acc += W3t[c*64 + f] * col[c];
    g_lhsW[f*NN + n] = acc;
    if (f == 0) {
        float bsum = 0.f;
        #pragma unroll 4
        for (int c = 0; c < 64; c++) bsum += b2[c] * col[c];
        g_lbias[n] = g_scal[0] * bsum;
    }
}

// ---------------- K0bc1/2: conv bias from b2 ----------------
__global__ void k0bc1(const float* __restrict__ b2, const float* __restrict__ tk) {
    int dt = blockIdx.x, u = threadIdx.x;
    float acc = 0.f;
    #pragma unroll 4
    for (int c = 0; c < 64; c++) acc += b2[c] * tk[(dt*64 + c)*64 + u];
    g_tbias[dt*64 + u] = acc;
}
__global__ void k0bc2() {
    int t = blockIdx.x, u = threadIdx.x;
    float acc = 0.f;
    #pragma unroll
    for (int dt = 0; dt < KLEN; dt++) {
        int tin = t + dt - 5;
        if (tin >= 0 && tin < TT) acc += g_tbias[dt*64 + u];
    }
    g_bc[t*64 + u] = acc;
}

// ---------------- K2: r1f, rhs, lhs per (b,t) — folded maps ----------------
__global__ void __launch_bounds__(512, 2)
k2_ta(const float* __restrict__ taW1) {
    __shared__ float r1s[64];
    int bt = blockIdx.x;
    int tid = threadIdx.x, lane = tid & 31, w = tid >> 5;
    if (tid < 64) r1s[tid] = 0.f;
    __syncthreads();
    float w3a = g_w3v[lane], w3b = g_w3v[lane + 32];
    float sb  = g_scal[1];
    float r0 = 0.f, r1a = 0.f;
    const float* yb = g_nodef + (size_t)bt*NN*UU;
    for (int n = w; n < NN; n += 16) {
        float yv0 = yb[n*64 + lane], yv1 = yb[n*64 + lane + 32];
        float w1v = taW1[n];
        r0  += w1v * yv0;
        r1a += w1v * yv1;
        float p = warp_sum(yv0 * w3a + yv1 * w3b);
        if (lane == 0) g_rhs[bt*NN + n] = p + sb;
    }
    atomicAdd(&r1s[lane], r0);
    atomicAdd(&r1s[lane + 32], r1a);
    __syncthreads();
    for (int n = tid; n < NN; n += 512) {
        float acc = g_lbias[n];
        #pragma unroll
        for (int f = 0; f < 64; f++) acc += r1s[f] * g_lhsW[f*NN + n];
        g_lhs[bt*NN + n] = acc;
    }
}

// ---------------- K3a: product + sigmoid ----------------
#define K3A_SMEM ((TT*401 + 15*401) * 4)
__global__ void __launch_bounds__(512, 1)
k3a_prod(const float* __restrict__ be) {
    extern __shared__ float sm[];
    float* rs = sm;
    float* ls = sm + TT*401;
    int b = blockIdx.x >> 2, chunk = blockIdx.x & 3;
    int t0 = chunk * 15;
    int tid = threadIdx.x;
    for (int i = tid; i < TT*NN; i += 512) {
        int s = i / NN, n = i - s*NN;
        rs[s*401 + n] = g_rhs[(b*TT + s)*NN + n];
    }
    for (int i = tid; i < 15*NN; i += 512) {
        int r = i / NN, n = i - r*NN;
        ls[r*401 + n] = g_lhs[(b*TT + t0 + r)*NN + n];
    }
    __syncthreads();
    for (int p = tid; p < 15*TT; p += 512) {
        int r = p / TT, s2 = p - r*TT;
        float acc = 0.f;
        #pragma unroll 4
        for (int n = 0; n < NN; n++) acc += ls[r*401 + n] * rs[s2*401 + n];
        acc += be[(t0 + r)*TT + s2];
        g_sg[(b*TT + t0 + r)*TT + s2] = 1.f / (1.f + expf(-acc));
    }
}

// ---------------- K3b: E = Ve @ sg, softmax over axis -2 ----------------
__global__ void __launch_bounds__(512, 2)
k3b_soft(const float* __restrict__ Ve) {
    __shared__ float sgs[TT*TT];
    __shared__ float Es [TT*TT];
    int b = blockIdx.x, tid = threadIdx.x;
    for (int i = tid; i < TT*TT; i += 512) sgs[i] = g_sg[b*TT*TT + i];
    __syncthreads();
    for (int p = tid; p < TT*TT; p += 512) {
        int j = p / TT, l = p - j*TT;
        float acc = 0.f;
        #pragma unroll 4
        for (int k = 0; k < TT; k++) acc += Ve[j*TT + k] * sgs[k*TT + l];
        Es[p] = acc;
    }
    __syncthreads();
    if (tid < TT) {
        int l = tid;
        float mx = -3.0e38f;
        for (int j = 0; j < TT; j++) mx = fmaxf(mx, Es[j*TT + l]);
        float s = 0.f;
        for (int j = 0; j < TT; j++) s += expf(Es[j*TT + l] - mx);
        float inv = 1.f / s;
        for (int j = 0; j < TT; j++)
            g_ker[(b*TT + j)*TT + l] = expf(Es[j*TT + l] - mx) * inv;
    }
}

// ---------------- K4: (ker·nodef | x) GEMM; warp = (m-pair, nhalf, khalf) ----------------
// 2 nodes/CTA, 512 threads, 2 CTAs/SM. Each warp: 2 m16-tiles x 4 n-tiles over half
// the K range -> every 1 KB B-load feeds 8 MMAs (halves L1 B traffic). khalf partials
// reduced through the az region (free after MMAs).
#define AZROWS (2*TPAD + 12)
#define K4_SMEM ((2*TT*UU + AZROWS*AZW) * 4)
__global__ void __launch_bounds__(512, 2)
k4_conv(const float* __restrict__ x,
        const float* __restrict__ tb, const float* __restrict__ rb,
        float* __restrict__ out) {
    extern __shared__ float sm[];
    float* ysp = sm;                      // 7680 (nodef staging)
    float* az  = sm + 2*TT*UU;            // AZROWS*AZW
    int b  = blockIdx.x / (NN/2);
    int np = blockIdx.x - b*(NN/2);
    int n0 = np * 2;
    int tid = threadIdx.x, lane = tid & 31, w = tid >> 5;
    const float* kerG = g_ker + b*TT*TT;

    for (int i = tid; i < 36*AZW; i += 512) {
        int z = i / AZW, f = i - z*AZW;
        int row;
        if (z < 24) {
            int nn = z / 12, r = z % 12;
            row = nn*TPAD + ((r < 5) ? r : r + 60);
        } else {
            row = 2*TPAD + (z - 24);
        }
        az[row*AZW + f] = 0.f;
    }
    for (int i = tid; i < 2*TT*32; i += 512) {
        int nn = i / (TT*32);
        int rr = i - nn*TT*32;
        int t  = rr >> 5, c2 = rr & 31;
        size_t gi = (((size_t)(b*TT + t))*NN + n0 + nn)*64 + 2*c2;
        *(float2*)(ysp + (nn*TT + t)*64 + 2*c2) = *(const float2*)(g_nodef + gi);
        float2 xv = *(const float2*)(x + gi);
        uint2 xr;
        xr.x = tf32r(xv.x);
        xr.y = tf32r(xv.y);
        *(uint2*)(az + (nn*TPAD + t + 5)*AZW + c2*4 + 2) = xr;
    }
    __syncthreads();

    // ---- phase 1: taf[m][f-pair] = sum_t ker[t][m] * nodef[t][f-pair], tf32-rounded ----
    {
        int nn = w >> 3, mg = w & 7;
        const float* yb = ysp + nn*TT*64;
        for (int m = mg; m < TT; m += 8) {
            unsigned long long acc2 = 0ull;
            #pragma unroll 4
            for (int t = 0; t < TT; t++) {
                float kv = kerG[t*TT + m];
                unsigned long long yv = *(const unsigned long long*)(yb + t*64 + 2*lane);
                ffma2(acc2, packf2(kv, kv), yv);
            }
            float r0, r1; unpackf2(acc2, r0, r1);
            uint2 tr;
            tr.x = tf32r(r0);
            tr.y = tf32r(r1);
            *(uint2*)(az + (nn*TPAD + m + 5)*AZW + lane*4) = tr;
        }
    }
    __syncthreads();

    // ---- phase 2: warp = (mp, nhalf, khalf); 2 m-tiles x 4 n-tiles x half-K ----
    int mp = w & 3, nhalf = (w >> 2) & 1, khalf = w >> 3;
    int gr = lane >> 2, ctg = lane & 3;
    const float* rp[4];
    int rnn[4], rtt[4]; bool rv[4];
    #pragma unroll
    for (int h = 0; h < 4; h++) {
        int ma = 32*mp + 8*h + gr;
        bool v = (ma < 120);
        rv[h]  = v;
        rnn[h] = v ? (ma / 60) : 0;
        rtt[h] = v ? (ma % 60) : 0;
        rp[h]  = az + (v ? (rnn[h]*TPAD + rtt[h]) : 2*TPAD) * AZW;
    }

    float acc[2][4][4];
    #pragma unroll
    for (int mm = 0; mm < 2; mm++)
        #pragma unroll
        for (int q = 0; q < 4; q++)
            #pragma unroll
            for (int i = 0; i < 4; i++) acc[mm][q][i] = 0.f;

    for (int dt = khalf*6; dt < khalf*6 + 6; dt++) {
        const float* r0p = rp[0] + dt*AZW;
        const float* r1p = rp[1] + dt*AZW;
        const float* r2p = rp[2] + dt*AZW;
        const float* r3p = rp[3] + dt*AZW;
        const float2* wf = g_wfrag + ((size_t)(dt*16))*8*32;
        #pragma unroll 4
        for (int inner = 0; inner < 16; inner++) {
            int fo = inner*8 + ctg;
            unsigned a00 = __float_as_uint(r0p[fo]);
            unsigned a02 = __float_as_uint(r0p[fo + 4]);
            unsigned a01 = __float_as_uint(r1p[fo]);
            unsigned a03 = __float_as_uint(r1p[fo + 4]);
            unsigned a10 = __float_as_uint(r2p[fo]);
            unsigned a12 = __float_as_uint(r2p[fo + 4]);
            unsigned a11 = __float_as_uint(r3p[fo]);
            unsigned a13 = __float_as_uint(r3p[fo + 4]);
            const float2* wi = wf + inner*8*32 + lane;
            #pragma unroll
            for (int q = 0; q < 4; q++) {
                float2 bv = wi[(nhalf*4 + q)*32];
                unsigned b0 = __float_as_uint(bv.x);
                unsigned b1 = __float_as_uint(bv.y);
                mma_tf32(acc[0][q], a00, a01, a02, a03, b0, b1);
                mma_tf32(acc[1][q], a10, a11, a12, a13, b0, b1);
            }
        }
    }

    // ---- k-split reduction through az (free after MMAs) ----
    __syncthreads();
    float* rbuf = az;
    if (khalf == 1) {
        float* dst = rbuf + (w - 8)*1024;
        #pragma unroll
        for (int mm = 0; mm < 2; mm++)
            #pragma unroll
            for (int q = 0; q < 4; q++)
                #pragma unroll
                for (int i = 0; i < 4; i++)
                    dst[((mm*4 + q)*4 + i)*32 + lane] = acc[mm][q][i];
    }
    __syncthreads();
    if (khalf == 0) {
        const float* src = rbuf + w*1024;
        #pragma unroll
        for (int mm = 0; mm < 2; mm++)
            #pragma unroll
            for (int q = 0; q < 4; q++)
                #pragma unroll
                for (int i = 0; i < 4; i++)
                    acc[mm][q][i] += src[((mm*4 + q)*4 + i)*32 + lane];

        // ---- epilogue: bias + softplus + store (khalf 0 warps only) ----
        #pragma unroll
        for (int mm = 0; mm < 2; mm++) {
            int ha = 2*mm, hb = 2*mm + 1;
            #pragma unroll
            for (int q = 0; q < 4; q++) {
                int col = (nhalf*4 + q)*8 + 2*ctg;
                float tbc0 = tb[col]     + rb[col];
                float tbc1 = tb[col + 1] + rb[col + 1];
                if (rv[ha]) {
                    size_t go = (((size_t)(b*TT + rtt[ha]))*NN + n0 + rnn[ha])*64 + col;
                    float2 o;
                    o.x = softplusf(acc[mm][q][0] + tbc0 + g_bc[rtt[ha]*64 + col]);
                    o.y = softplusf(acc[mm][q][1] + tbc1 + g_bc[rtt[ha]*64 + col + 1]);
                    *(float2*)(out + go) = o;
                }
                if (rv[hb]) {
                    size_t go = (((size_t)(b*TT + rtt[hb]))*NN + n0 + rnn[hb])*64 + col;
                    float2 o;
                    o.x = softplusf(acc[mm][q][2] + tbc0 + g_bc[rtt[hb]*64 + col]);
                    o.y = softplusf(acc[mm][q][3] + tbc1 + g_bc[rtt[hb]*64 + col + 1]);
                    *(float2*)(out + go) = o;
                }
            }
        }
    }
}

// ---------------- launch ----------------
extern "C" void kernel_launch(void* const* d_in, const int* in_sizes, int n_in,
                              void* d_out, int out_size) {
    const float* x    = (const float*)d_in[0];
    const float* A    = (const float*)d_in[1];
    const float* W1   = (const float*)d_in[2];
    const float* W2   = (const float*)d_in[3];
    const float* W3   = (const float*)d_in[4];
    const float* b1   = (const float*)d_in[5];
    const float* b2   = (const float*)d_in[6];
    const float* taW1 = (const float*)d_in[7];
    const float* taW2 = (const float*)d_in[8];
    const float* taW3 = (const float*)d_in[9];
    const float* Ve   = (const float*)d_in[10];
    const float* be   = (const float*)d_in[11];
    const float* tk   = (const float*)d_in[12];
    const float* tb   = (const float*)d_in[13];
    const float* rk   = (const float*)d_in[14];
    const float* rb   = (const float*)d_in[15];
    float* out = (float*)d_out;

    cudaFuncSetAttribute(k1_gc,    cudaFuncAttributeMaxDynamicSharedMemorySize, K1_SMEM);
    cudaFuncSetAttribute(k3a_prod, cudaFuncAttributeMaxDynamicSharedMemorySize, K3A_SMEM);
    cudaFuncSetAttribute(k4_conv,  cudaFuncAttributeMaxDynamicSharedMemorySize, K4_SMEM);

    k0w_fold<<<KLEN*64, 64>>>(tk, W3);          // 1
    k0_build<<<NN, 32>>>(A, W1, W2);            // 2
    k0b_pack<<<KSTEPS*8, 32>>>(rk);             // 3 (needs k0w)
    k1_gc<<<BT, 512, K1_SMEM>>>(x, b1);         // 4 <- profiled slot
    k0v_vec<<<1, 64>>>(W3, taW1, taW3, b2);     // 5
    k0l_fold<<<NN, 64>>>(W3, taW2, b2);         // 6 (needs k0v)
    k0bc1<<<KLEN, 64>>>(b2, tk);                // 7
    k0bc2<<<TT, 64>>>();                        // 8
    k2_ta<<<BT, 512>>>(taW1);                   // 9
    k3a_prod<<<BB*4, 512, K3A_SMEM>>>(be);
    k3b_soft<<<BB, 512>>>(Ve);
    k4_conv<<<BB*(NN/2), 512, K4_SMEM>>>(x, tb, rb, out);
}